// round 9
// baseline (speedup 1.0000x reference)
#include <cuda_runtime.h>
#include <cstdint>

// Problem constants (fixed by the reference: x,y are [8192, 1024] fp32)
#define N_ROWS 8192
#define D      1024
#define ROW_BYTES (D * 4)                     // 4096
#define TILE_ROWS 4
#define NTILES (N_ROWS / TILE_ROWS)           // 2048
#define TILE_BYTES (TILE_ROWS * ROW_BYTES)    // 16384 per input
#define NSTAGE 3
#define STAGE_BYTES (2 * TILE_BYTES)          // 32768 (x tile + y tile)
#define DATA_BYTES (NSTAGE * STAGE_BYTES)     // 98304 dynamic smem
#define GRID 296                              // 2 blocks/SM on 148 SMs
#define CONS_WARPS TILE_ROWS                  // 4 consumer warps (1 per row)
#define BLOCK_THREADS ((CONS_WARPS + 1) * 32) // 160

__device__ float g_partials[GRID];
__device__ unsigned int g_counter = 0;

// ---- PTX helpers --------------------------------------------------------
__device__ __forceinline__ uint32_t s2u(const void* p) {
    uint32_t a;
    asm("{ .reg .u64 t; cvta.to.shared.u64 t, %1; cvt.u32.u64 %0, t; }"
        : "=r"(a) : "l"(p));
    return a;
}
__device__ __forceinline__ void mbar_init(uint32_t m, uint32_t cnt) {
    asm volatile("mbarrier.init.shared.b64 [%0], %1;" :: "r"(m), "r"(cnt) : "memory");
}
__device__ __forceinline__ void mbar_expect_tx(uint32_t m, uint32_t bytes) {
    asm volatile("mbarrier.arrive.expect_tx.shared.b64 _, [%0], %1;"
                 :: "r"(m), "r"(bytes) : "memory");
}
__device__ __forceinline__ void mbar_arrive(uint32_t m) {
    asm volatile("mbarrier.arrive.shared.b64 _, [%0];" :: "r"(m) : "memory");
}
// Blocks while the barrier's current phase == parity.
__device__ __forceinline__ void mbar_wait(uint32_t m, uint32_t parity) {
    uint32_t done;
    do {
        asm volatile(
            "{\n\t.reg .pred p;\n\t"
            "mbarrier.try_wait.parity.acquire.cta.shared::cta.b64 p, [%1], %2, 0x989680;\n\t"
            "selp.b32 %0, 1, 0, p;\n\t}"
            : "=r"(done) : "r"(m), "r"(parity) : "memory");
    } while (!done);
}
__device__ __forceinline__ void bulk_g2s(uint32_t dst, const void* src,
                                         uint32_t bytes, uint32_t mbar) {
    asm volatile(
        "cp.async.bulk.shared::cta.global.mbarrier::complete_tx::bytes [%0], [%1], %2, [%3];"
        :: "r"(dst), "l"(src), "r"(bytes), "r"(mbar) : "memory");
}
// --------------------------------------------------------------------------

extern __shared__ char smem_data[];  // NSTAGE * STAGE_BYTES ring

__global__ __launch_bounds__(BLOCK_THREADS)
void row_loss_pipe_kernel(const float* __restrict__ x,
                          const float* __restrict__ y,
                          float* __restrict__ out) {
    __shared__ uint64_t full_mb[NSTAGE];
    __shared__ uint64_t empty_mb[NSTAGE];
    __shared__ float s_loss[CONS_WARPS];

    const int tid  = threadIdx.x;
    const int warp = tid >> 5;
    const int lane = tid & 31;

    if (tid == 0) {
        #pragma unroll
        for (int s = 0; s < NSTAGE; s++) {
            mbar_init(s2u(&full_mb[s]), 1);          // producer expect_tx arrive
            mbar_init(s2u(&empty_mb[s]), CONS_WARPS); // one arrive per consumer warp
        }
    }
    __syncthreads();

    if (warp == CONS_WARPS) {
        // ---- Producer: one elected thread streams tiles through the ring.
        if (lane == 0) {
            int stage = 0, phase = 1;  // parity 1 on fresh barrier -> first wait passes
            for (int t = blockIdx.x; t < NTILES; t += GRID) {
                mbar_wait(s2u(&empty_mb[stage]), phase);
                const uint32_t fm = s2u(&full_mb[stage]);
                const uint32_t dst = s2u(smem_data) + stage * STAGE_BYTES;
                mbar_expect_tx(fm, STAGE_BYTES);
                bulk_g2s(dst,              x + (size_t)t * TILE_ROWS * D, TILE_BYTES, fm);
                bulk_g2s(dst + TILE_BYTES, y + (size_t)t * TILE_ROWS * D, TILE_BYTES, fm);
                if (++stage == NSTAGE) { stage = 0; phase ^= 1; }
            }
        }
    } else {
        // ---- Consumer warp w: computes row w of each tile from smem.
        int stage = 0, phase = 0;
        float lsum = 0.0f;  // accumulated on lane 0 only
        for (int t = blockIdx.x; t < NTILES; t += GRID) {
            mbar_wait(s2u(&full_mb[stage]), phase);

            const char* base = smem_data + stage * STAGE_BYTES;
            const float4* __restrict__ xa =
                reinterpret_cast<const float4*>(base + warp * ROW_BYTES);
            const float4* __restrict__ ya =
                reinterpret_cast<const float4*>(base + TILE_BYTES + warp * ROW_BYTES);

            float dot = 0.0f, xx = 0.0f, yy = 0.0f;
            #pragma unroll
            for (int k = 0; k < 8; k++) {
                float4 a = xa[lane + 32 * k];
                float4 b = ya[lane + 32 * k];
                dot += a.x * b.x + a.y * b.y + a.z * b.z + a.w * b.w;
                xx  += a.x * a.x + a.y * a.y + a.z * a.z + a.w * a.w;
                yy  += b.x * b.x + b.y * b.y + b.z * b.z + b.w * b.w;
            }
            #pragma unroll
            for (int off = 16; off > 0; off >>= 1) {
                dot += __shfl_down_sync(0xFFFFFFFFu, dot, off);
                xx  += __shfl_down_sync(0xFFFFFFFFu, xx,  off);
                yy  += __shfl_down_sync(0xFFFFFFFFu, yy,  off);
            }
            // All lanes' reads are complete (shfl sync above); release buffer.
            if (lane == 0) {
                mbar_arrive(s2u(&empty_mb[stage]));
                float inv_norm = rsqrtf(fmaxf(xx * yy, 1e-24f));
                float cosv = dot * inv_norm;
                float arg  = fmaxf((cosv + 1.0f) * 0.5f, 1e-30f);
                lsum += -logf(arg);
            }
            if (++stage == NSTAGE) { stage = 0; phase ^= 1; }
        }
        if (lane == 0) s_loss[warp] = lsum;
    }
    __syncthreads();

    __shared__ bool s_is_last;
    if (tid == 0) {
        float t = 0.0f;
        #pragma unroll
        for (int i = 0; i < CONS_WARPS; i++) t += s_loss[i];
        g_partials[blockIdx.x] = t;
        __threadfence();
        unsigned int prev = atomicAdd(&g_counter, 1u);
        s_is_last = (prev == (unsigned int)(GRID - 1));
    }
    __syncthreads();

    // Single last-arriving block: deterministic fixed-order reduction of all
    // partials; re-arms the counter for the next graph replay.
    if (s_is_last) {
        float v = 0.0f;
        for (int idx = tid; idx < GRID; idx += BLOCK_THREADS)
            v += g_partials[idx];
        #pragma unroll
        for (int off = 16; off > 0; off >>= 1)
            v += __shfl_down_sync(0xFFFFFFFFu, v, off);

        __shared__ float s_fin[CONS_WARPS + 1];
        if (lane == 0) s_fin[warp] = v;
        __syncthreads();

        if (tid == 0) {
            float t = 0.0f;
            #pragma unroll
            for (int i = 0; i < CONS_WARPS + 1; i++) t += s_fin[i];
            out[0] = t * (1.0f / (float)N_ROWS);
            g_counter = 0;
        }
    }
}

extern "C" void kernel_launch(void* const* d_in, const int* in_sizes, int n_in,
                              void* d_out, int out_size) {
    const float* x = (const float*)d_in[0];
    const float* y = (const float*)d_in[1];
    float* out = (float*)d_out;

    cudaFuncSetAttribute(row_loss_pipe_kernel,
                         cudaFuncAttributeMaxDynamicSharedMemorySize, DATA_BYTES);
    row_loss_pipe_kernel<<<GRID, BLOCK_THREADS, DATA_BYTES>>>(x, y, out);
}

// round 10
// speedup vs baseline: 1.1188x; 1.1188x over previous
#include <cuda_runtime.h>

// Problem constants (fixed by the reference: x,y are [8192, 1024] fp32)
#define N_ROWS 8192
#define D      1024
#define WARPS_PER_BLOCK 8
#define NUM_BLOCKS (N_ROWS / WARPS_PER_BLOCK)  // 1024
#define BLOCK_THREADS (WARPS_PER_BLOCK * 32)   // 256

// Per-block partial sums of -log((cos+1)/2). Every slot is rewritten on every
// call before being read, so no reset pass is needed.
__device__ float g_partials[NUM_BLOCKS];
// Arrival counter for the last-block-done pattern. Starts at 0 (static init)
// and is reset to 0 by the last block each call -> graph-replay safe.
__device__ unsigned int g_counter = 0;

// Roofline note (rounds 1-9): this shape (LDG.128, 1 row/warp, 256-thread
// blocks, 32 regs, ~84% occ) sustains ~6.0 TB/s = the path-independent LTS
// full-chip byte/cycle cap. Wider loads (R3), more warps (R4), more regs
// (R5), L2 evict_last (R7), and TMA pipelines shallow/deep (R8/R9) all
// regressed or tied below it. 64MB mandatory traffic / LTS cap ~= 10.3us.
__global__ __launch_bounds__(BLOCK_THREADS)
void row_loss_fused_kernel(const float* __restrict__ x,
                           const float* __restrict__ y,
                           float* __restrict__ out) {
    const int warp = threadIdx.x >> 5;
    const int lane = threadIdx.x & 31;
    const int row  = blockIdx.x * WARPS_PER_BLOCK + warp;

    const float4* __restrict__ xr =
        reinterpret_cast<const float4*>(x + (size_t)row * D);
    const float4* __restrict__ yr =
        reinterpret_cast<const float4*>(y + (size_t)row * D);

    float dot = 0.0f, xx = 0.0f, yy = 0.0f;

    // 1024 floats/row = 256 float4. Lane l reads float4 indices l, l+32, ...
    // -> contiguous 512B warp bursts, 16 independent 16B loads per thread.
    #pragma unroll
    for (int k = 0; k < 8; k++) {
        float4 a = xr[lane + 32 * k];
        float4 b = yr[lane + 32 * k];
        dot += a.x * b.x + a.y * b.y + a.z * b.z + a.w * b.w;
        xx  += a.x * a.x + a.y * a.y + a.z * a.z + a.w * a.w;
        yy  += b.x * b.x + b.y * b.y + b.z * b.z + b.w * b.w;
    }

    // Warp tree reduction of the three accumulators.
    #pragma unroll
    for (int off = 16; off > 0; off >>= 1) {
        dot += __shfl_down_sync(0xFFFFFFFFu, dot, off);
        xx  += __shfl_down_sync(0xFFFFFFFFu, xx,  off);
        yy  += __shfl_down_sync(0xFFFFFFFFu, yy,  off);
    }

    __shared__ float s_loss[WARPS_PER_BLOCK];
    if (lane == 0) {
        float inv_norm = rsqrtf(fmaxf(xx * yy, 1e-24f));
        float cosv = dot * inv_norm;
        float arg  = fmaxf((cosv + 1.0f) * 0.5f, 1e-30f);
        s_loss[warp] = -logf(arg);
    }
    __syncthreads();

    __shared__ bool s_is_last;
    if (threadIdx.x == 0) {
        float t = 0.0f;
        #pragma unroll
        for (int i = 0; i < WARPS_PER_BLOCK; i++) t += s_loss[i];
        g_partials[blockIdx.x] = t;
        // Make the partial visible device-wide before signaling arrival.
        __threadfence();
        unsigned int prev = atomicAdd(&g_counter, 1u);
        s_is_last = (prev == (unsigned int)(NUM_BLOCKS - 1));
    }
    __syncthreads();

    // The single last-arriving block reduces all partials (fixed read order
    // -> deterministic result) and resets the counter for the next replay.
    if (s_is_last) {
        float v = 0.0f;
        #pragma unroll
        for (int i = 0; i < NUM_BLOCKS / BLOCK_THREADS; i++)
            v += g_partials[threadIdx.x + i * BLOCK_THREADS];

        #pragma unroll
        for (int off = 16; off > 0; off >>= 1)
            v += __shfl_down_sync(0xFFFFFFFFu, v, off);

        __shared__ float s_fin[WARPS_PER_BLOCK];
        if (lane == 0) s_fin[warp] = v;
        __syncthreads();

        if (threadIdx.x == 0) {
            float t = 0.0f;
            #pragma unroll
            for (int i = 0; i < WARPS_PER_BLOCK; i++) t += s_fin[i];
            out[0] = t * (1.0f / (float)N_ROWS);
            g_counter = 0;  // re-arm for next graph replay
        }
    }
}

extern "C" void kernel_launch(void* const* d_in, const int* in_sizes, int n_in,
                              void* d_out, int out_size) {
    const float* x = (const float*)d_in[0];
    const float* y = (const float*)d_in[1];
    float* out = (float*)d_out;

    row_loss_fused_kernel<<<NUM_BLOCKS, BLOCK_THREADS>>>(x, y, out);
}